// round 8
// baseline (speedup 1.0000x reference)
#include <cuda_runtime.h>
#include <math.h>

#define BB 8
#define NN 8192
#define IND 512
#define TD 512
#define NH 8
#define SCALE 0.125f

// ---------------- scratch (device globals; no runtime allocation) ----------
__device__ float g_q[(size_t)BB * NN * TD];        // normalized q   128MB
__device__ float g_u[(size_t)BB * NN * TD];        // U = k_norm*G   128MB
__device__ float g_logit[(size_t)BB * NH * NN];    // [b][h][n]
__device__ float g_ms[BB * NH * 2];                // (max, 1/sum)
__device__ float g_G[BB * TD];
__device__ float g_wc[64 * 1024];                  // [Wf@Wp | Wf], tf32-rounded
__device__ float g_bc[64];                         // Wf@bp + bf

// ---------------- helpers ---------------------------------------------------
__device__ __forceinline__ float tf32rn(float v) {
    unsigned u;
    asm("cvt.rna.tf32.f32 %0, %1;" : "=r"(u) : "f"(v));
    return __uint_as_float(u);
}

#define MMA8(d, a, b)                                                          \
    asm volatile(                                                              \
        "mma.sync.aligned.m16n8k8.row.col.f32.tf32.tf32.f32 "                  \
        "{%0,%1,%2,%3},{%4,%5,%6,%7},{%8,%9},{%0,%1,%2,%3};"                   \
        : "+f"((d)[0]), "+f"((d)[1]), "+f"((d)[2]), "+f"((d)[3])               \
        : "r"((a)[0]), "r"((a)[1]), "r"((a)[2]), "r"((a)[3]),                  \
          "r"((b)[0]), "r"((b)[1]))

#define LDST 36   // smem row stride in words (conflict-free)

// ===========================================================================
// K0: Wc = [Wf@Wp | Wf] (tf32-rounded), bc = Wf@bp + bf.   grid 64, 512 thr
// ===========================================================================
__global__ void k_wc(const float* __restrict__ Wp, const float* __restrict__ Wf,
                     const float* __restrict__ bp, const float* __restrict__ bf)
{
    __shared__ float wf[512];
    __shared__ float red[512];
    const int r = blockIdx.x, tid = threadIdx.x;
    wf[tid] = Wf[(size_t)r * 512 + tid];
    __syncthreads();
    float acc = 0.f;
    for (int k = 0; k < 512; ++k) acc += wf[k] * Wp[(size_t)k * 512 + tid];
    g_wc[(size_t)r * 1024 + tid] = tf32rn(acc);
    g_wc[(size_t)r * 1024 + 512 + tid] = tf32rn(wf[tid]);
    red[tid] = wf[tid] * bp[tid];
    __syncthreads();
    for (int s = 256; s > 0; s >>= 1) {
        if (tid < s) red[tid] += red[tid + s];
        __syncthreads();
    }
    if (tid == 0) g_bc[r] = red[0] + bf[r];
}

// ===========================================================================
// K1/K3a: tensor GEMM tile [128 tok x 128 cols], K=512, tf32 mma.sync.
//   mode 0: +bq, l2norm, logits -> g_q, g_logit
//   mode 1: +bk, l2norm, *G     -> g_u
// grid = B * 64 token-tiles * 4 col-chunks = 2048, 256 threads
// ===========================================================================
__global__ void __launch_bounds__(256, 2)
k_proj(const float* __restrict__ x, const float* __restrict__ W,
       const float* __restrict__ bias, const float* __restrict__ wg, int mode)
{
    extern __shared__ float sm[];
    float* Xh = sm;                    // [128][36]
    float* Ws = Xh + 128 * LDST;       // [128][36]

    const int tid  = threadIdx.x;
    const int wid  = tid >> 5, lane = tid & 31;
    const int grp  = lane >> 2, tig = lane & 3;
    const int wr   = wid & 3,  wc  = wid >> 2;

    const int bx  = blockIdx.x;
    const int bi  = bx >> 8;
    const int rem = bx & 255;
    const int nb  = rem & 3;           // col chunk (fastest: L2 reuse of X)
    const int t0  = (rem >> 2) << 7;   // token tile base

    const float* xb = x + ((size_t)bi * NN + t0) * IND;
    const float* Wb = W + (size_t)(nb * 128) * IND;

    float acc[2][8][4];
    #pragma unroll
    for (int mt = 0; mt < 2; ++mt)
        #pragma unroll
        for (int nt = 0; nt < 8; ++nt)
            #pragma unroll
            for (int j = 0; j < 4; ++j) acc[mt][nt][j] = 0.f;

    for (int kt = 0; kt < 16; ++kt) {
        __syncthreads();
        #pragma unroll
        for (int i = 0; i < 4; ++i) {            // X chunk [128,32] RN-tf32
            int e = tid + i * 256;
            int r = e >> 3, c4 = e & 7;
            float4 v = *(const float4*)(xb + (size_t)r * IND + kt * 32 + c4 * 4);
            v.x = tf32rn(v.x); v.y = tf32rn(v.y);
            v.z = tf32rn(v.z); v.w = tf32rn(v.w);
            *(float4*)(Xh + r * LDST + c4 * 4) = v;
        }
        #pragma unroll
        for (int i = 0; i < 4; ++i) {            // W chunk [128,32] RN-tf32
            int e = tid + i * 256;
            int r = e >> 3, c4 = e & 7;
            float4 v = *(const float4*)(Wb + (size_t)r * IND + kt * 32 + c4 * 4);
            v.x = tf32rn(v.x); v.y = tf32rn(v.y);
            v.z = tf32rn(v.z); v.w = tf32rn(v.w);
            *(float4*)(Ws + r * LDST + c4 * 4) = v;
        }
        __syncthreads();

        #pragma unroll
        for (int ks = 0; ks < 4; ++ks) {
            const int kb = ks * 8;
            unsigned ah[2][4], bfr[8][2];
            #pragma unroll
            for (int mt = 0; mt < 2; ++mt) {
                const int r0 = wr * 32 + mt * 16 + grp;
                ah[mt][0] = __float_as_uint(Xh[r0 * LDST + kb + tig]);
                ah[mt][1] = __float_as_uint(Xh[(r0 + 8) * LDST + kb + tig]);
                ah[mt][2] = __float_as_uint(Xh[r0 * LDST + kb + tig + 4]);
                ah[mt][3] = __float_as_uint(Xh[(r0 + 8) * LDST + kb + tig + 4]);
            }
            #pragma unroll
            for (int nt = 0; nt < 8; ++nt) {
                const int c0 = wc * 64 + nt * 8 + grp;
                bfr[nt][0] = __float_as_uint(Ws[c0 * LDST + kb + tig]);
                bfr[nt][1] = __float_as_uint(Ws[c0 * LDST + kb + tig + 4]);
            }
            #pragma unroll
            for (int mt = 0; mt < 2; ++mt)
                #pragma unroll
                for (int nt = 0; nt < 8; ++nt)
                    MMA8(acc[mt][nt], ah[mt], bfr[nt]);
        }
    }

    // ---------------- epilogue: bias, l2norm, logits / *G --------------------
    const int ghead = nb * 2 + wc;
    float* base = (mode == 0 ? g_q : g_u);
    #pragma unroll
    for (int mt = 0; mt < 2; ++mt)
        #pragma unroll
        for (int s = 0; s < 2; ++s) {
            const int row = wr * 32 + mt * 16 + s * 8 + grp;
            const int token = t0 + row;
            float v[16];
            float ss = 0.f;
            #pragma unroll
            for (int nt = 0; nt < 8; ++nt)
                #pragma unroll
                for (int j = 0; j < 2; ++j) {
                    const int cih = nt * 8 + tig * 2 + j;
                    float val = acc[mt][nt][s * 2 + j] + bias[ghead * 64 + cih];
                    v[nt * 2 + j] = val;
                    ss += val * val;
                }
            ss += __shfl_xor_sync(0xFFFFFFFFu, ss, 1);
            ss += __shfl_xor_sync(0xFFFFFFFFu, ss, 2);
            const float inv = 1.f / fmaxf(sqrtf(ss), 1e-12f);
            if (mode == 0) {
                float lg = 0.f;
                #pragma unroll
                for (int nt = 0; nt < 8; ++nt)
                    #pragma unroll
                    for (int j = 0; j < 2; ++j)
                        lg += v[nt * 2 + j] * wg[ghead * 64 + nt * 8 + tig * 2 + j];
                lg += __shfl_xor_sync(0xFFFFFFFFu, lg, 1);
                lg += __shfl_xor_sync(0xFFFFFFFFu, lg, 2);
                if (tig == 0)
                    g_logit[((size_t)(bi * NH + ghead)) * NN + token] = lg * inv * SCALE;
                #pragma unroll
                for (int j = 0; j < 16; ++j) v[j] *= inv;
            } else {
                #pragma unroll
                for (int nt = 0; nt < 8; ++nt)
                    #pragma unroll
                    for (int j = 0; j < 2; ++j)
                        v[nt * 2 + j] *= inv * g_G[bi * TD + ghead * 64 + nt * 8 + tig * 2 + j];
            }
            float* dst = base + ((size_t)bi * NN + token) * TD + ghead * 64;
            #pragma unroll
            for (int nt = 0; nt < 8; ++nt)
                *(float2*)(dst + nt * 8 + tig * 2) = make_float2(v[nt * 2], v[nt * 2 + 1]);
        }
}

// ===========================================================================
// K2a: softmax stats per (b,h) + zero G.  grid 64, 256 threads
// ===========================================================================
__global__ void k_stats(void)
{
    __shared__ float red[256];
    const int b = blockIdx.x >> 3, h = blockIdx.x & 7, tid = threadIdx.x;
    const float* L = g_logit + ((size_t)(b * NH + h)) * NN;
    float m = -1e30f;
    for (int n = tid; n < NN; n += 256) m = fmaxf(m, L[n]);
    red[tid] = m; __syncthreads();
    for (int s = 128; s > 0; s >>= 1) {
        if (tid < s) red[tid] = fmaxf(red[tid], red[tid + s]);
        __syncthreads();
    }
    m = red[0]; __syncthreads();
    float sum = 0.f;
    for (int n = tid; n < NN; n += 256) sum += expf(L[n] - m);
    red[tid] = sum; __syncthreads();
    for (int s = 128; s > 0; s >>= 1) {
        if (tid < s) red[tid] += red[tid + s];
        __syncthreads();
    }
    if (tid == 0) {
        g_ms[(b * NH + h) * 2] = m;
        g_ms[(b * NH + h) * 2 + 1] = 1.f / red[0];
    }
    if (tid < 64) g_G[b * TD + h * 64 + tid] = 0.f;
}

// ===========================================================================
// K2b: G accumulation.  grid 1024 (b x 128 chunks of 64 tokens), 256 threads
// ===========================================================================
__global__ void __launch_bounds__(256) k_accG(void)
{
    __shared__ float ws[8 * 64];
    __shared__ float ms[16];
    const int b = blockIdx.x >> 7, n0 = (blockIdx.x & 127) * 64, tid = threadIdx.x;
    if (tid < 16) ms[tid] = g_ms[b * 16 + tid];
    __syncthreads();
    for (int i = tid; i < 512; i += 256) {
        int h = i >> 6, t = i & 63;
        ws[i] = expf(g_logit[((size_t)(b * NH + h)) * NN + n0 + t] - ms[h * 2]) * ms[h * 2 + 1];
    }
    __syncthreads();
    const int d0 = tid, d1 = tid + 256;
    const int h0 = d0 >> 6, h1 = d1 >> 6;
    float a0 = 0.f, a1 = 0.f;
    const float* qb = g_q + ((size_t)b * NN + n0) * TD;
    #pragma unroll 4
    for (int t = 0; t < 64; ++t) {
        a0 += ws[h0 * 64 + t] * qb[(size_t)t * TD + d0];
        a1 += ws[h1 * 64 + t] * qb[(size_t)t * TD + d1];
    }
    atomicAdd(&g_G[b * TD + d0], a0);
    atomicAdd(&g_G[b * TD + d1], a1);
}

// ===========================================================================
// K3b: out = [U|q] @ Wc^T + bc  (M=128, N=64, K=1024). grid 512, 256 threads
// ===========================================================================
__global__ void __launch_bounds__(256, 2) k_out(float* __restrict__ out)
{
    extern __shared__ float sm[];
    float* Ah = sm;                    // [128][36]
    float* Bs = Ah + 128 * LDST;       // [64][36]

    const int tid  = threadIdx.x;
    const int wid  = tid >> 5, lane = tid & 31;
    const int grp  = lane >> 2, tig = lane & 3;
    const int bi   = blockIdx.x >> 6;
    const int t0   = (blockIdx.x & 63) << 7;

    float acc[8][4];
    #pragma unroll
    for (int nt = 0; nt < 8; ++nt)
        #pragma unroll
        for (int j = 0; j < 4; ++j) acc[nt][j] = 0.f;

    for (int kt = 0; kt < 32; ++kt) {
        const float* A = (kt < 16 ? g_u : g_q) + ((size_t)bi * NN + t0) * TD + (kt & 15) * 32;
        __syncthreads();
        #pragma unroll
        for (int i = 0; i < 4; ++i) {
            int e = tid + i * 256;
            int r = e >> 3, c4 = e & 7;
            float4 v = *(const float4*)(A + (size_t)r * TD + c4 * 4);
            v.x = tf32rn(v.x); v.y = tf32rn(v.y);
            v.z = tf32rn(v.z); v.w = tf32rn(v.w);
            *(float4*)(Ah + r * LDST + c4 * 4) = v;
        }
        #pragma unroll
        for (int i = 0; i < 2; ++i) {            // B chunk [64,32], pre-rounded
            int e = tid + i * 256;
            int r = e >> 3, c4 = e & 7;
            float4 v = *(const float4*)(g_wc + (size_t)r * 1024 + kt * 32 + c4 * 4);
            *(float4*)(Bs + r * LDST + c4 * 4) = v;
        }
        __syncthreads();

        #pragma unroll
        for (int ks = 0; ks < 4; ++ks) {
            const int kb = ks * 8;
            unsigned ah[4], bfr[8][2];
            const int r0 = wid * 16 + grp;
            ah[0] = __float_as_uint(Ah[r0 * LDST + kb + tig]);
            ah[1] = __float_as_uint(Ah[(r0 + 8) * LDST + kb + tig]);
            ah[2] = __float_as_uint(Ah[r0 * LDST + kb + tig + 4]);
            ah[3] = __float_as_uint(Ah[(r0 + 8) * LDST + kb + tig + 4]);
            #pragma unroll
            for (int nt = 0; nt < 8; ++nt) {
                const int c0 = nt * 8 + grp;
                bfr[nt][0] = __float_as_uint(Bs[c0 * LDST + kb + tig]);
                bfr[nt][1] = __float_as_uint(Bs[c0 * LDST + kb + tig + 4]);
            }
            #pragma unroll
            for (int nt = 0; nt < 8; ++nt)
                MMA8(acc[nt], ah, bfr[nt]);
        }
    }

    #pragma unroll
    for (int s = 0; s < 2; ++s) {
        const int row = wid * 16 + s * 8 + grp;
        const int token = t0 + row;
        float* orow = out + ((size_t)bi * NN + token) * 64;
        #pragma unroll
        for (int nt = 0; nt < 8; ++nt) {
            const int c = nt * 8 + tig * 2;
            float2 v = make_float2(acc[nt][s * 2] + g_bc[c],
                                   acc[nt][s * 2 + 1] + g_bc[c + 1]);
            *(float2*)(orow + c) = v;
        }
    }
}

// ===========================================================================
extern "C" void kernel_launch(void* const* d_in, const int* in_sizes, int n_in,
                              void* d_out, int out_size)
{
    (void)in_sizes; (void)n_in; (void)out_size;
    const float* x  = (const float*)d_in[0];
    const float* Wq = (const float*)d_in[1];
    const float* bq = (const float*)d_in[2];
    const float* Wk = (const float*)d_in[3];
    const float* bk = (const float*)d_in[4];
    const float* wg = (const float*)d_in[5];
    const float* Wp = (const float*)d_in[6];
    const float* bp = (const float*)d_in[7];
    const float* Wf = (const float*)d_in[8];
    const float* bf = (const float*)d_in[9];
    float* out = (float*)d_out;

    const int smem_proj = 2 * 128 * LDST * (int)sizeof(float);              // 36864
    const int smem_out  = (128 + 64) * LDST * (int)sizeof(float);           // 27648
    cudaFuncSetAttribute(k_proj, cudaFuncAttributeMaxDynamicSharedMemorySize, smem_proj);
    cudaFuncSetAttribute(k_out,  cudaFuncAttributeMaxDynamicSharedMemorySize, smem_out);

    k_wc<<<64, 512>>>(Wp, Wf, bp, bf);
    k_proj<<<2048, 256, smem_proj>>>(x, Wq, bq, wg, 0);
    k_stats<<<64, 256>>>();
    k_accG<<<1024, 256>>>();
    k_proj<<<2048, 256, smem_proj>>>(x, Wk, bk, wg, 1);
    k_out<<<512, 256, smem_out>>>(out);
}